// round 1
// baseline (speedup 1.0000x reference)
#include <cuda_runtime.h>
#include <cuda_bf16.h>

// ---------------------------------------------------------------------------
// miScore: out[i,k] = (1/256) * sum_j sigmoid( y_a[i,:] . (W @ y_b[j,:] + b) )
//
// Stage 1: proj[j,s] = sum_t y_b[j,t]*W[s,t] + b[s]      (8192x256x256 GEMM-NT)
// Stage 2: s[i]     += sum_j sigmoid(y_a[i,:].proj[j,:])  (8192x8192x256 fused)
// Stage 3: out[i,k]  = s[i] / 256                         (broadcast)
// ---------------------------------------------------------------------------

#define NUSR 8192
#define HDIM 256

#define BM 64
#define BN 64
#define BK 16
#define LDS_PAD 68   // BM + 4 padding to dodge bank conflicts on transposed store

// Scratch (no cudaMalloc allowed)
__device__ float g_proj[NUSR * HDIM];   // 8 MB
__device__ float g_s[NUSR];             // row sums

// ---------------------------------------------------------------------------
__global__ void zero_s_kernel() {
    g_s[blockIdx.x * 256 + threadIdx.x] = 0.0f;
}

// ---------------------------------------------------------------------------
// Stage 1: proj = y_b @ W^T + b.  A = y_b [8192,256], B = W [256,256], both
// row-major K-contiguous (NT GEMM). Grid: (HDIM/BN=4, NUSR/BM=128).
__global__ __launch_bounds__(256, 2)
void proj_gemm_kernel(const float* __restrict__ Yb,
                      const float* __restrict__ W,
                      const float* __restrict__ bias) {
    __shared__ float As[BK][LDS_PAD];
    __shared__ float Bs[BK][LDS_PAD];

    const int K = HDIM;
    const int j0 = blockIdx.y * BM;
    const int s0 = blockIdx.x * BN;
    const int tid = threadIdx.x;
    const int tx = tid & 15;        // 0..15 -> output col group
    const int ty = tid >> 4;        // 0..15 -> output row group
    const int lr = tid >> 2;        // 0..63 load row
    const int lk = (tid & 3) * 4;   // 0,4,8,12 load k offset

    float acc[4][4] = {};

    for (int kt = 0; kt < K; kt += BK) {
        float4 av = *(const float4*)&Yb[(size_t)(j0 + lr) * K + kt + lk];
        float4 bv = *(const float4*)&W [(size_t)(s0 + lr) * K + kt + lk];
        __syncthreads();   // previous tile's reads done
        As[lk + 0][lr] = av.x; As[lk + 1][lr] = av.y;
        As[lk + 2][lr] = av.z; As[lk + 3][lr] = av.w;
        Bs[lk + 0][lr] = bv.x; Bs[lk + 1][lr] = bv.y;
        Bs[lk + 2][lr] = bv.z; Bs[lk + 3][lr] = bv.w;
        __syncthreads();

        #pragma unroll
        for (int kk = 0; kk < BK; kk++) {
            float4 a = *(const float4*)&As[kk][ty * 4];
            float4 b = *(const float4*)&Bs[kk][tx * 4];
            acc[0][0] += a.x * b.x; acc[0][1] += a.x * b.y;
            acc[0][2] += a.x * b.z; acc[0][3] += a.x * b.w;
            acc[1][0] += a.y * b.x; acc[1][1] += a.y * b.y;
            acc[1][2] += a.y * b.z; acc[1][3] += a.y * b.w;
            acc[2][0] += a.z * b.x; acc[2][1] += a.z * b.y;
            acc[2][2] += a.z * b.z; acc[2][3] += a.z * b.w;
            acc[3][0] += a.w * b.x; acc[3][1] += a.w * b.y;
            acc[3][2] += a.w * b.z; acc[3][3] += a.w * b.w;
        }
    }

    #pragma unroll
    for (int m = 0; m < 4; m++) {
        const int row = j0 + ty * 4 + m;
        #pragma unroll
        for (int n = 0; n < 4; n++) {
            const int col = s0 + tx * 4 + n;
            g_proj[(size_t)row * HDIM + col] = acc[m][n] + bias[col];
        }
    }
}

// ---------------------------------------------------------------------------
// Stage 2: fused scores GEMM + sigmoid + row reduce.
// A = y_a [8192,256], B = g_proj [8192,256] (NT). Grid: (128, 128).
__global__ __launch_bounds__(256, 2)
void fused_score_kernel(const float* __restrict__ Ya) {
    __shared__ float As[BK][LDS_PAD];
    __shared__ float Bs[BK][LDS_PAD];

    const int K = HDIM;
    const int i0 = blockIdx.y * BM;   // output row tile (users i)
    const int j0 = blockIdx.x * BN;   // reduced dim tile (users j)
    const int tid = threadIdx.x;
    const int tx = tid & 15;
    const int ty = tid >> 4;
    const int lr = tid >> 2;
    const int lk = (tid & 3) * 4;

    float acc[4][4] = {};

    #pragma unroll 1
    for (int kt = 0; kt < K; kt += BK) {
        float4 av = *(const float4*)&Ya    [(size_t)(i0 + lr) * K + kt + lk];
        float4 bv = *(const float4*)&g_proj[(size_t)(j0 + lr) * K + kt + lk];
        __syncthreads();
        As[lk + 0][lr] = av.x; As[lk + 1][lr] = av.y;
        As[lk + 2][lr] = av.z; As[lk + 3][lr] = av.w;
        Bs[lk + 0][lr] = bv.x; Bs[lk + 1][lr] = bv.y;
        Bs[lk + 2][lr] = bv.z; Bs[lk + 3][lr] = bv.w;
        __syncthreads();

        #pragma unroll
        for (int kk = 0; kk < BK; kk++) {
            float4 a = *(const float4*)&As[kk][ty * 4];
            float4 b = *(const float4*)&Bs[kk][tx * 4];
            acc[0][0] += a.x * b.x; acc[0][1] += a.x * b.y;
            acc[0][2] += a.x * b.z; acc[0][3] += a.x * b.w;
            acc[1][0] += a.y * b.x; acc[1][1] += a.y * b.y;
            acc[1][2] += a.y * b.z; acc[1][3] += a.y * b.w;
            acc[2][0] += a.z * b.x; acc[2][1] += a.z * b.y;
            acc[2][2] += a.z * b.z; acc[2][3] += a.z * b.w;
            acc[3][0] += a.w * b.x; acc[3][1] += a.w * b.y;
            acc[3][2] += a.w * b.z; acc[3][3] += a.w * b.w;
        }
    }

    // Epilogue: sigmoid each score, sum over the 4 local columns, reduce
    // across the 16 tx lanes sharing each row, atomically add to g_s.
    #pragma unroll
    for (int m = 0; m < 4; m++) {
        float r = 0.0f;
        #pragma unroll
        for (int n = 0; n < 4; n++) {
            // sigmoid(x) = 1 / (1 + e^-x); saturates correctly at +-inf
            r += __fdividef(1.0f, 1.0f + __expf(-acc[m][n]));
        }
        // reduce within each 16-lane half-warp (tx group)
        r += __shfl_down_sync(0xffffffffu, r, 8, 16);
        r += __shfl_down_sync(0xffffffffu, r, 4, 16);
        r += __shfl_down_sync(0xffffffffu, r, 2, 16);
        r += __shfl_down_sync(0xffffffffu, r, 1, 16);
        if (tx == 0) {
            atomicAdd(&g_s[i0 + ty * 4 + m], r);
        }
    }
}

// ---------------------------------------------------------------------------
// Stage 3: out[i,k] = g_s[i] / 256, vectorized float4 stores.
__global__ void broadcast_kernel(float* __restrict__ out) {
    const int idx = blockIdx.x * 256 + threadIdx.x;   // float4 index
    const int row = idx >> 6;                          // 64 float4 per row
    const float v = g_s[row] * (1.0f / 256.0f);
    ((float4*)out)[idx] = make_float4(v, v, v, v);
}

// ---------------------------------------------------------------------------
extern "C" void kernel_launch(void* const* d_in, const int* in_sizes, int n_in,
                              void* d_out, int out_size) {
    const float* y_a = (const float*)d_in[0];
    const float* y_b = (const float*)d_in[1];
    const float* W   = (const float*)d_in[2];
    const float* b   = (const float*)d_in[3];
    float* out = (float*)d_out;

    zero_s_kernel<<<NUSR / 256, 256>>>();
    proj_gemm_kernel<<<dim3(HDIM / BN, NUSR / BM), 256>>>(y_b, W, b);
    fused_score_kernel<<<dim3(NUSR / BN, NUSR / BM), 256>>>(y_a);
    broadcast_kernel<<<(NUSR * HDIM / 4) / 256, 256>>>(out);
}

// round 3
// speedup vs baseline: 4.2570x; 4.2570x over previous
#include <cuda_runtime.h>
#include <cuda_bf16.h>
#include <cstdint>

// ---------------------------------------------------------------------------
// miScore: out[i,k] = (1/256) * sum_j sigmoid( y_a[i,:] . (W @ y_b[j,:] + b) )
//
// tcgen05 is NOT accepted by this harness's ptxas target (sm_103 w/o 'a'),
// so the big GEMM uses classic mma.sync (HMMA) bf16 with fp32 accumulation.
//
// S0: convert y_a fp32 -> bf16                      (g_ya)
// S1: proj = y_b @ W^T + b (fp32 FFMA, bf16 store)  (g_projb)
// S2: fused HMMA bf16 GEMM (y_a @ proj^T) + sigmoid + row partials
// S3: reduce 64 partials -> g_s ; broadcast to out
// ---------------------------------------------------------------------------

#define NUSR 8192
#define HDIM 256

__device__ __align__(16) __nv_bfloat16 g_ya[NUSR * HDIM];     // 4 MB
__device__ __align__(16) __nv_bfloat16 g_projb[NUSR * HDIM];  // 4 MB
__device__ float g_part[64][NUSR];                            // 2 MB
__device__ float g_s[NUSR];

// ---------------- cp.async helpers ----------------
__device__ __forceinline__ void cp_async16(uint32_t dst, const void* src) {
    asm volatile("cp.async.cg.shared.global [%0], [%1], 16;" :: "r"(dst), "l"(src));
}
#define CP_COMMIT() asm volatile("cp.async.commit_group;" ::: "memory")
#define CP_WAIT1()  asm volatile("cp.async.wait_group 1;" ::: "memory")
#define CP_WAIT0()  asm volatile("cp.async.wait_group 0;" ::: "memory")

// ---------------- mma / ldmatrix ----------------
__device__ __forceinline__ void ldsm_x4(uint32_t* r, uint32_t addr) {
    asm volatile("ldmatrix.sync.aligned.m8n8.x4.shared.b16 {%0,%1,%2,%3}, [%4];"
                 : "=r"(r[0]), "=r"(r[1]), "=r"(r[2]), "=r"(r[3]) : "r"(addr));
}
__device__ __forceinline__ void mma16816(float* c, const uint32_t* a, const uint32_t* b) {
    asm volatile(
        "mma.sync.aligned.m16n8k16.row.col.f32.bf16.bf16.f32 "
        "{%0,%1,%2,%3}, {%4,%5,%6,%7}, {%8,%9}, {%0,%1,%2,%3};"
        : "+f"(c[0]), "+f"(c[1]), "+f"(c[2]), "+f"(c[3])
        : "r"(a[0]), "r"(a[1]), "r"(a[2]), "r"(a[3]), "r"(b[0]), "r"(b[1]));
}

// ===========================================================================
// S0: y_a fp32 -> bf16
// ===========================================================================
__global__ void convert_ya_kernel(const float* __restrict__ ya) {
    const int idx = blockIdx.x * 256 + threadIdx.x;        // one float4 each
    float4 v = ((const float4*)ya)[idx];
    __nv_bfloat162* dst = (__nv_bfloat162*)g_ya;
    dst[idx * 2 + 0] = __floats2bfloat162_rn(v.x, v.y);
    dst[idx * 2 + 1] = __floats2bfloat162_rn(v.z, v.w);
}

// ===========================================================================
// S1: proj = y_b @ W^T + b (fp32 compute, bf16 store). 1 GFLOP.
// ===========================================================================
#define BM 64
#define BN 64
#define BKP 16
#define LDS_PAD 68

__global__ __launch_bounds__(256, 2)
void proj_gemm_kernel(const float* __restrict__ Yb,
                      const float* __restrict__ W,
                      const float* __restrict__ bias) {
    __shared__ float As[BKP][LDS_PAD];
    __shared__ float Bs[BKP][LDS_PAD];

    const int K = HDIM;
    const int j0 = blockIdx.y * BM;
    const int s0 = blockIdx.x * BN;
    const int tid = threadIdx.x;
    const int tx = tid & 15, ty = tid >> 4;
    const int lr = tid >> 2, lk = (tid & 3) * 4;

    float acc[4][4] = {};

    for (int kt = 0; kt < K; kt += BKP) {
        float4 av = *(const float4*)&Yb[(size_t)(j0 + lr) * K + kt + lk];
        float4 bv = *(const float4*)&W [(size_t)(s0 + lr) * K + kt + lk];
        __syncthreads();
        As[lk + 0][lr] = av.x; As[lk + 1][lr] = av.y;
        As[lk + 2][lr] = av.z; As[lk + 3][lr] = av.w;
        Bs[lk + 0][lr] = bv.x; Bs[lk + 1][lr] = bv.y;
        Bs[lk + 2][lr] = bv.z; Bs[lk + 3][lr] = bv.w;
        __syncthreads();

        #pragma unroll
        for (int kk = 0; kk < BKP; kk++) {
            float4 a = *(const float4*)&As[kk][ty * 4];
            float4 b = *(const float4*)&Bs[kk][tx * 4];
            acc[0][0] += a.x * b.x; acc[0][1] += a.x * b.y;
            acc[0][2] += a.x * b.z; acc[0][3] += a.x * b.w;
            acc[1][0] += a.y * b.x; acc[1][1] += a.y * b.y;
            acc[1][2] += a.y * b.z; acc[1][3] += a.y * b.w;
            acc[2][0] += a.z * b.x; acc[2][1] += a.z * b.y;
            acc[2][2] += a.z * b.z; acc[2][3] += a.z * b.w;
            acc[3][0] += a.w * b.x; acc[3][1] += a.w * b.y;
            acc[3][2] += a.w * b.z; acc[3][3] += a.w * b.w;
        }
    }

    const int col = s0 + tx * 4;
    const float b0 = bias[col], b1 = bias[col + 1], b2 = bias[col + 2], b3 = bias[col + 3];
    #pragma unroll
    for (int m = 0; m < 4; m++) {
        const int row = j0 + ty * 4 + m;
        __nv_bfloat162 lo = __floats2bfloat162_rn(acc[m][0] + b0, acc[m][1] + b1);
        __nv_bfloat162 hi = __floats2bfloat162_rn(acc[m][2] + b2, acc[m][3] + b3);
        *((__nv_bfloat162*)&g_projb[(size_t)row * HDIM + col])     = lo;
        *((__nv_bfloat162*)&g_projb[(size_t)row * HDIM + col + 2]) = hi;
    }
}

// ===========================================================================
// S2: fused HMMA bf16 GEMM + sigmoid + per-(i, jblock) row partials.
//   CTA tile 128(M=i) x 128(N=j), K=256 in 8 chunks of 32 (double-buffered).
//   8 warps as 4(M) x 2(N); warp tile 32x64; mma m16n8k16.
//   SMEM rows padded to 40 bf16 (80 B) -> ldmatrix conflict-free.
// ===========================================================================
#define SROW 40   // 32 + 8 pad (bf16 elements per smem row)

__global__ __launch_bounds__(256, 2)
void fused_hmma_kernel() {
    __shared__ __nv_bfloat16 sA[2][128][SROW];
    __shared__ __nv_bfloat16 sB[2][128][SROW];
    __shared__ float s_rows[2][128];

    const int tid = threadIdx.x;
    const int wid = tid >> 5, lane = tid & 31;
    const int wm0 = (wid >> 1) * 32;           // warp M offset
    const int wn0 = (wid & 1) * 64;            // warp N offset
    const int i0 = blockIdx.y * 128;
    const int j0 = blockIdx.x * 128;

    const uint32_t sA_u = (uint32_t)__cvta_generic_to_shared(&sA[0][0][0]);
    const uint32_t sB_u = (uint32_t)__cvta_generic_to_shared(&sB[0][0][0]);
    const uint32_t bufA_bytes = 128 * SROW * 2;
    const uint32_t bufB_bytes = 128 * SROW * 2;

    // ---- load lambda: copy one 128x32 bf16 k-chunk each for A and B ----
    // 512 granules of 16B per matrix; 256 threads -> 2 granules each.
    const int g0 = tid, g1 = tid + 256;
    const int r0 = g0 >> 2, c0 = g0 & 3;
    const int r1 = g1 >> 2, c1 = g1 & 3;

    float acc[2][8][4];
    #pragma unroll
    for (int mt = 0; mt < 2; mt++)
        #pragma unroll
        for (int nt = 0; nt < 8; nt++)
            #pragma unroll
            for (int e = 0; e < 4; e++) acc[mt][nt][e] = 0.0f;

    // prologue: k-chunk 0 into buf 0
    {
        const __nv_bfloat16* a_src = g_ya    + (size_t)(i0 + r0) * HDIM + c0 * 8;
        const __nv_bfloat16* b_src = g_projb + (size_t)(j0 + r0) * HDIM + c0 * 8;
        cp_async16(sA_u + (r0 * SROW + c0 * 8) * 2, a_src);
        cp_async16(sB_u + (r0 * SROW + c0 * 8) * 2, b_src);
        const __nv_bfloat16* a_src1 = g_ya    + (size_t)(i0 + r1) * HDIM + c1 * 8;
        const __nv_bfloat16* b_src1 = g_projb + (size_t)(j0 + r1) * HDIM + c1 * 8;
        cp_async16(sA_u + (r1 * SROW + c1 * 8) * 2, a_src1);
        cp_async16(sB_u + (r1 * SROW + c1 * 8) * 2, b_src1);
        CP_COMMIT();
    }

    int buf = 0;
    #pragma unroll 1
    for (int it = 0; it < 8; it++) {
        if (it < 7) {
            const int kt = (it + 1) * 32;
            const uint32_t dA = sA_u + (1 - buf) * bufA_bytes;
            const uint32_t dB = sB_u + (1 - buf) * bufB_bytes;
            cp_async16(dA + (r0 * SROW + c0 * 8) * 2,
                       g_ya + (size_t)(i0 + r0) * HDIM + kt + c0 * 8);
            cp_async16(dB + (r0 * SROW + c0 * 8) * 2,
                       g_projb + (size_t)(j0 + r0) * HDIM + kt + c0 * 8);
            cp_async16(dA + (r1 * SROW + c1 * 8) * 2,
                       g_ya + (size_t)(i0 + r1) * HDIM + kt + c1 * 8);
            cp_async16(dB + (r1 * SROW + c1 * 8) * 2,
                       g_projb + (size_t)(j0 + r1) * HDIM + kt + c1 * 8);
            CP_COMMIT();
            CP_WAIT1();
        } else {
            CP_WAIT0();
        }
        __syncthreads();

        const uint32_t aBase = sA_u + buf * bufA_bytes;
        const uint32_t bBase = sB_u + buf * bufB_bytes;
        const int sub = lane >> 3;      // 0..3
        const int r8  = lane & 7;       // 0..7

        #pragma unroll
        for (int kk = 0; kk < 32; kk += 16) {
            // A fragments: 2 m-tiles, one ldmatrix.x4 each
            uint32_t afrag[2][4];
            #pragma unroll
            for (int mt = 0; mt < 2; mt++) {
                int row = wm0 + mt * 16 + (sub & 1) * 8 + r8;
                int col = kk + (sub >> 1) * 8;
                ldsm_x4(afrag[mt], aBase + (row * SROW + col) * 2);
            }
            // B fragments: 8 n-tiles, 4 ldmatrix.x4 (2 n-tiles each)
            uint32_t bfrag[8][2];
            #pragma unroll
            for (int p = 0; p < 4; p++) {
                int row = wn0 + p * 16 + (sub >> 1) * 8 + r8;
                int col = kk + (sub & 1) * 8;
                uint32_t t[4];
                ldsm_x4(t, bBase + (row * SROW + col) * 2);
                bfrag[p * 2 + 0][0] = t[0]; bfrag[p * 2 + 0][1] = t[1];
                bfrag[p * 2 + 1][0] = t[2]; bfrag[p * 2 + 1][1] = t[3];
            }
            #pragma unroll
            for (int mt = 0; mt < 2; mt++)
                #pragma unroll
                for (int nt = 0; nt < 8; nt++)
                    mma16816(acc[mt][nt], afrag[mt], bfrag[nt]);
        }
        __syncthreads();
        buf ^= 1;
    }

    // ---- epilogue: sigmoid + row reduce ----
    // c-frag layout: c0,c1 -> row (wm0+mt*16+lane/4),      cols 2*(lane%4)+{0,1}
    //                c2,c3 -> row (wm0+mt*16+8+lane/4), same cols
    float rs[2][2] = {};   // [mt][half-row]
    #pragma unroll
    for (int mt = 0; mt < 2; mt++)
        #pragma unroll
        for (int nt = 0; nt < 8; nt++) {
            rs[mt][0] += __fdividef(1.0f, 1.0f + __expf(-acc[mt][nt][0]))
                       + __fdividef(1.0f, 1.0f + __expf(-acc[mt][nt][1]));
            rs[mt][1] += __fdividef(1.0f, 1.0f + __expf(-acc[mt][nt][2]))
                       + __fdividef(1.0f, 1.0f + __expf(-acc[mt][nt][3]));
        }
    // reduce across the 4 lanes of each quad (they hold different n columns)
    #pragma unroll
    for (int mt = 0; mt < 2; mt++)
        #pragma unroll
        for (int h = 0; h < 2; h++) {
            rs[mt][h] += __shfl_xor_sync(0xffffffffu, rs[mt][h], 1);
            rs[mt][h] += __shfl_xor_sync(0xffffffffu, rs[mt][h], 2);
        }
    if ((lane & 3) == 0) {
        const int rq = lane >> 2;      // 0..7
        const int wn = wid & 1;
        #pragma unroll
        for (int mt = 0; mt < 2; mt++) {
            s_rows[wn][wm0 + mt * 16 + 0 + rq] = rs[mt][0];
            s_rows[wn][wm0 + mt * 16 + 8 + rq] = rs[mt][1];
        }
    }
    __syncthreads();
    if (tid < 128) {
        g_part[blockIdx.x][i0 + tid] = s_rows[0][tid] + s_rows[1][tid];
    }
}

// ===========================================================================
// S3: reduce 64 partials, broadcast.
// ===========================================================================
__global__ void reduce_kernel() {
    const int i = blockIdx.x * 256 + threadIdx.x;
    float s = 0.0f;
    #pragma unroll
    for (int t = 0; t < 64; t++) s += g_part[t][i];
    g_s[i] = s * (1.0f / 256.0f);
}

__global__ void broadcast_kernel(float* __restrict__ out) {
    const int idx = blockIdx.x * 256 + threadIdx.x;   // float4 index
    const int row = idx >> 6;
    const float v = g_s[row];
    ((float4*)out)[idx] = make_float4(v, v, v, v);
}

// ===========================================================================
extern "C" void kernel_launch(void* const* d_in, const int* in_sizes, int n_in,
                              void* d_out, int out_size) {
    const float* y_a = (const float*)d_in[0];
    const float* y_b = (const float*)d_in[1];
    const float* W   = (const float*)d_in[2];
    const float* b   = (const float*)d_in[3];
    float* out = (float*)d_out;

    convert_ya_kernel<<<(NUSR * HDIM / 4) / 256, 256>>>(y_a);
    proj_gemm_kernel<<<dim3(HDIM / BN, NUSR / BM), 256>>>(y_b, W, b);
    fused_hmma_kernel<<<dim3(NUSR / 128, NUSR / 128), 256>>>();
    reduce_kernel<<<NUSR / 256, 256>>>();
    broadcast_kernel<<<(NUSR * HDIM / 4) / 256, 256>>>(out);
}

// round 4
// speedup vs baseline: 4.9347x; 1.1592x over previous
#include <cuda_runtime.h>
#include <cuda_bf16.h>
#include <cstdint>

// ---------------------------------------------------------------------------
// miScore: out[i,k] = (1/256) * sum_j sigmoid( y_a[i,:] . (W @ y_b[j,:] + b) )
//
// S0: convert y_a fp32 -> bf16                      (g_ya)
// S1: proj = y_b @ W^T + b (fp32 FFMA, bf16 store)  (g_projb)
// S2: fused HMMA bf16 GEMM (y_a @ proj^T) + sigmoid + row partials
//     CTA tile 128x256, warp tile 64x64, K=256 in 8 double-buffered chunks
// S3: reduce 32 partials + broadcast (one warp per row)
// ---------------------------------------------------------------------------

#define NUSR 8192
#define HDIM 256

__device__ __align__(16) __nv_bfloat16 g_ya[NUSR * HDIM];     // 4 MB
__device__ __align__(16) __nv_bfloat16 g_projb[NUSR * HDIM];  // 4 MB
__device__ float g_part[32][NUSR];                            // 1 MB
__device__ float g_s[NUSR];

// ---------------- cp.async helpers ----------------
__device__ __forceinline__ void cp_async16(uint32_t dst, const void* src) {
    asm volatile("cp.async.cg.shared.global [%0], [%1], 16;" :: "r"(dst), "l"(src));
}
#define CP_COMMIT() asm volatile("cp.async.commit_group;" ::: "memory")
#define CP_WAIT1()  asm volatile("cp.async.wait_group 1;" ::: "memory")
#define CP_WAIT0()  asm volatile("cp.async.wait_group 0;" ::: "memory")

// ---------------- mma / ldmatrix ----------------
__device__ __forceinline__ void ldsm_x4(uint32_t* r, uint32_t addr) {
    asm volatile("ldmatrix.sync.aligned.m8n8.x4.shared.b16 {%0,%1,%2,%3}, [%4];"
                 : "=r"(r[0]), "=r"(r[1]), "=r"(r[2]), "=r"(r[3]) : "r"(addr));
}
__device__ __forceinline__ void mma16816(float* c, const uint32_t* a, const uint32_t* b) {
    asm volatile(
        "mma.sync.aligned.m16n8k16.row.col.f32.bf16.bf16.f32 "
        "{%0,%1,%2,%3}, {%4,%5,%6,%7}, {%8,%9}, {%0,%1,%2,%3};"
        : "+f"(c[0]), "+f"(c[1]), "+f"(c[2]), "+f"(c[3])
        : "r"(a[0]), "r"(a[1]), "r"(a[2]), "r"(a[3]), "r"(b[0]), "r"(b[1]));
}

// ===========================================================================
// S0: y_a fp32 -> bf16
// ===========================================================================
__global__ void convert_ya_kernel(const float* __restrict__ ya) {
    const int idx = blockIdx.x * 256 + threadIdx.x;        // one float4 each
    float4 v = ((const float4*)ya)[idx];
    __nv_bfloat162* dst = (__nv_bfloat162*)g_ya;
    dst[idx * 2 + 0] = __floats2bfloat162_rn(v.x, v.y);
    dst[idx * 2 + 1] = __floats2bfloat162_rn(v.z, v.w);
}

// ===========================================================================
// S1: proj = y_b @ W^T + b (fp32 compute, bf16 store). 1 GFLOP.
// ===========================================================================
#define BM 64
#define BN 64
#define BKP 16
#define LDS_PAD 68

__global__ __launch_bounds__(256, 2)
void proj_gemm_kernel(const float* __restrict__ Yb,
                      const float* __restrict__ W,
                      const float* __restrict__ bias) {
    __shared__ float As[BKP][LDS_PAD];
    __shared__ float Bs[BKP][LDS_PAD];

    const int K = HDIM;
    const int j0 = blockIdx.y * BM;
    const int s0 = blockIdx.x * BN;
    const int tid = threadIdx.x;
    const int tx = tid & 15, ty = tid >> 4;
    const int lr = tid >> 2, lk = (tid & 3) * 4;

    float acc[4][4] = {};

    for (int kt = 0; kt < K; kt += BKP) {
        float4 av = *(const float4*)&Yb[(size_t)(j0 + lr) * K + kt + lk];
        float4 bv = *(const float4*)&W [(size_t)(s0 + lr) * K + kt + lk];
        __syncthreads();
        As[lk + 0][lr] = av.x; As[lk + 1][lr] = av.y;
        As[lk + 2][lr] = av.z; As[lk + 3][lr] = av.w;
        Bs[lk + 0][lr] = bv.x; Bs[lk + 1][lr] = bv.y;
        Bs[lk + 2][lr] = bv.z; Bs[lk + 3][lr] = bv.w;
        __syncthreads();

        #pragma unroll
        for (int kk = 0; kk < BKP; kk++) {
            float4 a = *(const float4*)&As[kk][ty * 4];
            float4 b = *(const float4*)&Bs[kk][tx * 4];
            acc[0][0] += a.x * b.x; acc[0][1] += a.x * b.y;
            acc[0][2] += a.x * b.z; acc[0][3] += a.x * b.w;
            acc[1][0] += a.y * b.x; acc[1][1] += a.y * b.y;
            acc[1][2] += a.y * b.z; acc[1][3] += a.y * b.w;
            acc[2][0] += a.z * b.x; acc[2][1] += a.z * b.y;
            acc[2][2] += a.z * b.z; acc[2][3] += a.z * b.w;
            acc[3][0] += a.w * b.x; acc[3][1] += a.w * b.y;
            acc[3][2] += a.w * b.z; acc[3][3] += a.w * b.w;
        }
    }

    const int col = s0 + tx * 4;
    const float b0 = bias[col], b1 = bias[col + 1], b2 = bias[col + 2], b3 = bias[col + 3];
    #pragma unroll
    for (int m = 0; m < 4; m++) {
        const int row = j0 + ty * 4 + m;
        __nv_bfloat162 lo = __floats2bfloat162_rn(acc[m][0] + b0, acc[m][1] + b1);
        __nv_bfloat162 hi = __floats2bfloat162_rn(acc[m][2] + b2, acc[m][3] + b3);
        *((__nv_bfloat162*)&g_projb[(size_t)row * HDIM + col])     = lo;
        *((__nv_bfloat162*)&g_projb[(size_t)row * HDIM + col + 2]) = hi;
    }
}

// ===========================================================================
// S2: fused HMMA bf16 GEMM + sigmoid + per-(i, jblock) row partials.
//   CTA 128(M=i) x 256(N=j); 8 warps as 2(M) x 4(N); warp tile 64x64.
//   K=256 in 8 chunks of 32, double-buffered cp.async.
//   SMEM rows padded to 40 bf16 (80 B) -> ldmatrix conflict-free.
// ===========================================================================
#define SROW 40
#define SA_BYTES (128 * SROW * 2)            // 10240
#define SB_BYTES (256 * SROW * 2)            // 20480
#define BUF_BYTES (SA_BYTES + SB_BYTES)      // 30720
#define SROWS_OFF (2 * BUF_BYTES)            // 61440
#define FUSED_SMEM (SROWS_OFF + 4 * 128 * 4) // 63488

__global__ void __launch_bounds__(256, 1) fused_hmma_kernel() {
    extern __shared__ __align__(16) char smem[];
    const uint32_t sbase = (uint32_t)__cvta_generic_to_shared(smem);
    float* s_rows = (float*)(smem + SROWS_OFF);   // [4][128]

    const int tid = threadIdx.x;
    const int wid = tid >> 5, lane = tid & 31;
    const int wm0 = (wid & 1) * 64;            // warp M offset (0 / 64)
    const int wn0 = (wid >> 1) * 64;           // warp N offset (0/64/128/192)
    const int i0 = blockIdx.y * 128;
    const int j0 = blockIdx.x * 256;

    float acc[4][8][4];
    #pragma unroll
    for (int mt = 0; mt < 4; mt++)
        #pragma unroll
        for (int nt = 0; nt < 8; nt++)
            #pragma unroll
            for (int e = 0; e < 4; e++) acc[mt][nt][e] = 0.0f;

    // ---- loader: 1536 granules of 16 B (A: 512, B: 1024); 6 per thread ----
    auto load_chunk = [&](uint32_t dst, int kt) {
        #pragma unroll
        for (int t = 0; t < 6; t++) {
            int g = tid + t * 256;
            if (g < 512) {
                int row = g >> 2, c = g & 3;
                cp_async16(dst + (row * SROW + c * 8) * 2,
                           g_ya + (size_t)(i0 + row) * HDIM + kt + c * 8);
            } else {
                int gb = g - 512;
                int row = gb >> 2, c = gb & 3;
                cp_async16(dst + SA_BYTES + (row * SROW + c * 8) * 2,
                           g_projb + (size_t)(j0 + row) * HDIM + kt + c * 8);
            }
        }
        CP_COMMIT();
    };

    load_chunk(sbase, 0);

    const int sub = lane >> 3;      // 0..3
    const int r8  = lane & 7;       // 0..7

    int buf = 0;
    #pragma unroll 1
    for (int it = 0; it < 8; it++) {
        if (it < 7) {
            load_chunk(sbase + (1 - buf) * BUF_BYTES, (it + 1) * 32);
            CP_WAIT1();
        } else {
            CP_WAIT0();
        }
        __syncthreads();

        const uint32_t aBase = sbase + buf * BUF_BYTES;
        const uint32_t bBase = aBase + SA_BYTES;

        #pragma unroll
        for (int kk = 0; kk < 32; kk += 16) {
            uint32_t afrag[4][4];
            #pragma unroll
            for (int mt = 0; mt < 4; mt++) {
                int row = wm0 + mt * 16 + (sub & 1) * 8 + r8;
                int col = kk + (sub >> 1) * 8;
                ldsm_x4(afrag[mt], aBase + (row * SROW + col) * 2);
            }
            uint32_t bfrag[8][2];
            #pragma unroll
            for (int p = 0; p < 4; p++) {
                int row = wn0 + p * 16 + (sub >> 1) * 8 + r8;
                int col = kk + (sub & 1) * 8;
                uint32_t t[4];
                ldsm_x4(t, bBase + (row * SROW + col) * 2);
                bfrag[p * 2 + 0][0] = t[0]; bfrag[p * 2 + 0][1] = t[1];
                bfrag[p * 2 + 1][0] = t[2]; bfrag[p * 2 + 1][1] = t[3];
            }
            #pragma unroll
            for (int mt = 0; mt < 4; mt++)
                #pragma unroll
                for (int nt = 0; nt < 8; nt++)
                    mma16816(acc[mt][nt], afrag[mt], bfrag[nt]);
        }
        __syncthreads();
        buf ^= 1;
    }

    // ---- epilogue: sigmoid + row reduce ----
    // c-frag: c0,c1 -> row (wm0+mt*16+lane/4),   cols wn0+nt*8+2*(lane%4)+{0,1}
    //         c2,c3 -> row (wm0+mt*16+8+lane/4), same cols
    float rs[4][2];
    #pragma unroll
    for (int mt = 0; mt < 4; mt++) { rs[mt][0] = 0.0f; rs[mt][1] = 0.0f; }
    #pragma unroll
    for (int mt = 0; mt < 4; mt++)
        #pragma unroll
        for (int nt = 0; nt < 8; nt++) {
            rs[mt][0] += __fdividef(1.0f, 1.0f + __expf(-acc[mt][nt][0]))
                       + __fdividef(1.0f, 1.0f + __expf(-acc[mt][nt][1]));
            rs[mt][1] += __fdividef(1.0f, 1.0f + __expf(-acc[mt][nt][2]))
                       + __fdividef(1.0f, 1.0f + __expf(-acc[mt][nt][3]));
        }
    #pragma unroll
    for (int mt = 0; mt < 4; mt++)
        #pragma unroll
        for (int h = 0; h < 2; h++) {
            rs[mt][h] += __shfl_xor_sync(0xffffffffu, rs[mt][h], 1);
            rs[mt][h] += __shfl_xor_sync(0xffffffffu, rs[mt][h], 2);
        }
    if ((lane & 3) == 0) {
        const int rq = lane >> 2;                  // 0..7
        const int wn = wid >> 1;                   // 0..3
        #pragma unroll
        for (int mt = 0; mt < 4; mt++) {
            s_rows[wn * 128 + wm0 + mt * 16 + 0 + rq] = rs[mt][0];
            s_rows[wn * 128 + wm0 + mt * 16 + 8 + rq] = rs[mt][1];
        }
    }
    __syncthreads();
    if (tid < 128) {
        g_part[blockIdx.x][i0 + tid] = s_rows[tid] + s_rows[128 + tid] +
                                       s_rows[256 + tid] + s_rows[384 + tid];
    }
}

// ===========================================================================
// S3: reduce 32 partials + broadcast. One warp per output row.
// ===========================================================================
__global__ void reduce_bcast_kernel(float* __restrict__ out) {
    const int wid = threadIdx.x >> 5, lane = threadIdx.x & 31;
    const int row = blockIdx.x * 8 + wid;
    float s = g_part[lane][row];
    #pragma unroll
    for (int d = 16; d > 0; d >>= 1) s += __shfl_xor_sync(0xffffffffu, s, d);
    const float v = s * (1.0f / 256.0f);
    float4* dst = (float4*)(out + (size_t)row * HDIM);
    const float4 vv = make_float4(v, v, v, v);
    dst[lane]      = vv;
    dst[lane + 32] = vv;
}

// ===========================================================================
extern "C" void kernel_launch(void* const* d_in, const int* in_sizes, int n_in,
                              void* d_out, int out_size) {
    const float* y_a = (const float*)d_in[0];
    const float* y_b = (const float*)d_in[1];
    const float* W   = (const float*)d_in[2];
    const float* b   = (const float*)d_in[3];
    float* out = (float*)d_out;

    cudaFuncSetAttribute(fused_hmma_kernel,
                         cudaFuncAttributeMaxDynamicSharedMemorySize, FUSED_SMEM);

    convert_ya_kernel<<<(NUSR * HDIM / 4) / 256, 256>>>(y_a);
    proj_gemm_kernel<<<dim3(HDIM / BN, NUSR / BM), 256>>>(y_b, W, b);
    fused_hmma_kernel<<<dim3(NUSR / 256, NUSR / 128), 256, FUSED_SMEM>>>();
    reduce_bcast_kernel<<<NUSR / 8, 256>>>(out);
}

// round 5
// speedup vs baseline: 6.4754x; 1.3122x over previous
#include <cuda_runtime.h>
#include <cuda_bf16.h>
#include <cstdint>

// ---------------------------------------------------------------------------
// miScore: out[i,k] = (1/256) * sum_j sigmoid( y_a[i,:] . (W @ y_b[j,:] + b) )
//
// S0: convert y_a, y_b, W fp32 -> bf16 (one kernel)
// S1: proj = y_b @ W^T + b   (HMMA bf16, bias epilogue, bf16 store)
// S2: fused HMMA bf16 GEMM (y_a @ proj^T) + sigmoid + row partials
//     CTA 128x256, warp 64x64, K=256 in 4 double-buffered BK=64 chunks
// S3: reduce 32 partials + broadcast (one warp per row)
// ---------------------------------------------------------------------------

#define NUSR 8192
#define HDIM 256

__device__ __align__(16) __nv_bfloat16 g_ya[NUSR * HDIM];     // 4 MB
__device__ __align__(16) __nv_bfloat16 g_yb[NUSR * HDIM];     // 4 MB
__device__ __align__(16) __nv_bfloat16 g_wb[HDIM * HDIM];     // 128 KB
__device__ __align__(16) __nv_bfloat16 g_projb[NUSR * HDIM];  // 4 MB
__device__ float g_part[32][NUSR];                            // 1 MB
__device__ float g_s[NUSR];

// ---------------- cp.async helpers ----------------
__device__ __forceinline__ void cp_async16(uint32_t dst, const void* src) {
    asm volatile("cp.async.cg.shared.global [%0], [%1], 16;" :: "r"(dst), "l"(src));
}
#define CP_COMMIT() asm volatile("cp.async.commit_group;" ::: "memory")
#define CP_WAIT1()  asm volatile("cp.async.wait_group 1;" ::: "memory")
#define CP_WAIT0()  asm volatile("cp.async.wait_group 0;" ::: "memory")

// ---------------- mma / ldmatrix ----------------
__device__ __forceinline__ void ldsm_x4(uint32_t* r, uint32_t addr) {
    asm volatile("ldmatrix.sync.aligned.m8n8.x4.shared.b16 {%0,%1,%2,%3}, [%4];"
                 : "=r"(r[0]), "=r"(r[1]), "=r"(r[2]), "=r"(r[3]) : "r"(addr));
}
__device__ __forceinline__ void mma16816(float* c, const uint32_t* a, const uint32_t* b) {
    asm volatile(
        "mma.sync.aligned.m16n8k16.row.col.f32.bf16.bf16.f32 "
        "{%0,%1,%2,%3}, {%4,%5,%6,%7}, {%8,%9}, {%0,%1,%2,%3};"
        : "+f"(c[0]), "+f"(c[1]), "+f"(c[2]), "+f"(c[3])
        : "r"(a[0]), "r"(a[1]), "r"(a[2]), "r"(a[3]), "r"(b[0]), "r"(b[1]));
}

// ===========================================================================
// S0: convert y_a, y_b, W to bf16. One float4 per thread.
//   float4 counts: y_a 524288, y_b 524288, W 16384  -> 1064960 = 4160 * 256
// ===========================================================================
__global__ void convert_all_kernel(const float* __restrict__ ya,
                                   const float* __restrict__ yb,
                                   const float* __restrict__ W) {
    const int idx = blockIdx.x * 256 + threadIdx.x;
    const float* src;
    __nv_bfloat162* dst;
    int off;
    if (idx < 524288) {
        src = ya; dst = (__nv_bfloat162*)g_ya; off = idx;
    } else if (idx < 1048576) {
        src = yb; dst = (__nv_bfloat162*)g_yb; off = idx - 524288;
    } else {
        src = W;  dst = (__nv_bfloat162*)g_wb; off = idx - 1048576;
    }
    float4 v = ((const float4*)src)[off];
    dst[off * 2 + 0] = __floats2bfloat162_rn(v.x, v.y);
    dst[off * 2 + 1] = __floats2bfloat162_rn(v.z, v.w);
}

// ===========================================================================
// S1: proj = y_b @ W^T + b (HMMA). CTA 128(Mj) x 128(Ns); grid (2, 64).
//   8 warps as 2(M) x 4(N); warp tile 64x32. K=256 in 8 BK=32 chunks.
// ===========================================================================
#define PSROW 40
#define PA_BYTES (128 * PSROW * 2)
#define PBUF_BYTES (2 * PA_BYTES)

__global__ void __launch_bounds__(256, 1) proj_hmma_kernel(const float* __restrict__ bias) {
    __shared__ __align__(16) char smem[2 * PBUF_BYTES];
    const uint32_t sbase = (uint32_t)__cvta_generic_to_shared(smem);

    const int tid = threadIdx.x;
    const int wid = tid >> 5, lane = tid & 31;
    const int wm0 = (wid & 1) * 64;
    const int wn0 = (wid >> 1) * 32;
    const int j0 = blockIdx.y * 128;
    const int s0 = blockIdx.x * 128;

    float acc[4][4][4];
    #pragma unroll
    for (int mt = 0; mt < 4; mt++)
        #pragma unroll
        for (int nt = 0; nt < 4; nt++)
            #pragma unroll
            for (int e = 0; e < 4; e++) acc[mt][nt][e] = 0.0f;

    auto load_chunk = [&](uint32_t dstb, int kt) {
        #pragma unroll
        for (int t = 0; t < 4; t++) {
            int g = tid + t * 256;
            if (g < 512) {
                int row = g >> 2, c = g & 3;
                cp_async16(dstb + (row * PSROW + c * 8) * 2,
                           g_yb + (size_t)(j0 + row) * HDIM + kt + c * 8);
            } else {
                int gb = g - 512;
                int row = gb >> 2, c = gb & 3;
                cp_async16(dstb + PA_BYTES + (row * PSROW + c * 8) * 2,
                           g_wb + (size_t)(s0 + row) * HDIM + kt + c * 8);
            }
        }
        CP_COMMIT();
    };

    load_chunk(sbase, 0);

    const int sub = lane >> 3, r8 = lane & 7;

    int buf = 0;
    #pragma unroll 1
    for (int it = 0; it < 8; it++) {
        if (it < 7) { load_chunk(sbase + (1 - buf) * PBUF_BYTES, (it + 1) * 32); CP_WAIT1(); }
        else        { CP_WAIT0(); }
        __syncthreads();

        const uint32_t aBase = sbase + buf * PBUF_BYTES;
        const uint32_t bBase = aBase + PA_BYTES;

        #pragma unroll
        for (int kk = 0; kk < 32; kk += 16) {
            uint32_t afrag[4][4];
            #pragma unroll
            for (int mt = 0; mt < 4; mt++) {
                int row = wm0 + mt * 16 + (sub & 1) * 8 + r8;
                int col = kk + (sub >> 1) * 8;
                ldsm_x4(afrag[mt], aBase + (row * PSROW + col) * 2);
            }
            uint32_t bfrag[4][2];
            #pragma unroll
            for (int p = 0; p < 2; p++) {
                int row = wn0 + p * 16 + (sub >> 1) * 8 + r8;
                int col = kk + (sub & 1) * 8;
                uint32_t t4[4];
                ldsm_x4(t4, bBase + (row * PSROW + col) * 2);
                bfrag[p * 2 + 0][0] = t4[0]; bfrag[p * 2 + 0][1] = t4[1];
                bfrag[p * 2 + 1][0] = t4[2]; bfrag[p * 2 + 1][1] = t4[3];
            }
            #pragma unroll
            for (int mt = 0; mt < 4; mt++)
                #pragma unroll
                for (int nt = 0; nt < 4; nt++)
                    mma16816(acc[mt][nt], afrag[mt], bfrag[nt]);
        }
        __syncthreads();
        buf ^= 1;
    }

    // epilogue: + bias, store bf16
    #pragma unroll
    for (int nt = 0; nt < 4; nt++) {
        const int gc = s0 + wn0 + nt * 8 + 2 * (lane & 3);
        const float b0 = bias[gc], b1 = bias[gc + 1];
        #pragma unroll
        for (int mt = 0; mt < 4; mt++) {
            const int rlo = j0 + wm0 + mt * 16 + (lane >> 2);
            *((__nv_bfloat162*)&g_projb[(size_t)rlo * HDIM + gc]) =
                __floats2bfloat162_rn(acc[mt][nt][0] + b0, acc[mt][nt][1] + b1);
            *((__nv_bfloat162*)&g_projb[(size_t)(rlo + 8) * HDIM + gc]) =
                __floats2bfloat162_rn(acc[mt][nt][2] + b0, acc[mt][nt][3] + b1);
        }
    }
}

// ===========================================================================
// S2: fused HMMA bf16 GEMM + sigmoid + row partials.
//   CTA 128(M=i) x 256(N=j); 8 warps 2(M) x 4(N); warp tile 64x64.
//   K=256 in 4 chunks of 64, double-buffered cp.async.
//   SMEM rows padded to 72 bf16 (144 B) -> ldmatrix conflict-free.
// ===========================================================================
#define SROW 72
#define SA_BYTES (128 * SROW * 2)            // 18432
#define SB_BYTES (256 * SROW * 2)            // 36864
#define BUF_BYTES (SA_BYTES + SB_BYTES)      // 55296
#define SROWS_OFF (2 * BUF_BYTES)            // 110592
#define FUSED_SMEM (SROWS_OFF + 4 * 128 * 4) // 112640

__global__ void __launch_bounds__(256, 1) fused_hmma_kernel() {
    extern __shared__ __align__(16) char smem[];
    const uint32_t sbase = (uint32_t)__cvta_generic_to_shared(smem);
    float* s_rows = (float*)(smem + SROWS_OFF);   // [4][128]

    const int tid = threadIdx.x;
    const int wid = tid >> 5, lane = tid & 31;
    const int wm0 = (wid & 1) * 64;            // warp M offset
    const int wn0 = (wid >> 1) * 64;           // warp N offset
    const int i0 = blockIdx.y * 128;
    const int j0 = blockIdx.x * 256;

    float acc[4][8][4];
    #pragma unroll
    for (int mt = 0; mt < 4; mt++)
        #pragma unroll
        for (int nt = 0; nt < 8; nt++)
            #pragma unroll
            for (int e = 0; e < 4; e++) acc[mt][nt][e] = 0.0f;

    // loader: A 1024 + B 2048 granules of 16 B; 12 per thread
    auto load_chunk = [&](uint32_t dstb, int kt) {
        #pragma unroll
        for (int t = 0; t < 12; t++) {
            int g = tid + t * 256;
            if (g < 1024) {
                int row = g >> 3, c = g & 7;
                cp_async16(dstb + (row * SROW + c * 8) * 2,
                           g_ya + (size_t)(i0 + row) * HDIM + kt + c * 8);
            } else {
                int gb = g - 1024;
                int row = gb >> 3, c = gb & 7;
                cp_async16(dstb + SA_BYTES + (row * SROW + c * 8) * 2,
                           g_projb + (size_t)(j0 + row) * HDIM + kt + c * 8);
            }
        }
        CP_COMMIT();
    };

    load_chunk(sbase, 0);

    const int sub = lane >> 3, r8 = lane & 7;

    int buf = 0;
    #pragma unroll 1
    for (int it = 0; it < 4; it++) {
        if (it < 3) { load_chunk(sbase + (1 - buf) * BUF_BYTES, (it + 1) * 64); CP_WAIT1(); }
        else        { CP_WAIT0(); }
        __syncthreads();

        const uint32_t aBase = sbase + buf * BUF_BYTES;
        const uint32_t bBase = aBase + SA_BYTES;

        #pragma unroll
        for (int kk = 0; kk < 64; kk += 16) {
            uint32_t afrag[4][4];
            #pragma unroll
            for (int mt = 0; mt < 4; mt++) {
                int row = wm0 + mt * 16 + (sub & 1) * 8 + r8;
                int col = kk + (sub >> 1) * 8;
                ldsm_x4(afrag[mt], aBase + (row * SROW + col) * 2);
            }
            uint32_t bfrag[8][2];
            #pragma unroll
            for (int p = 0; p < 4; p++) {
                int row = wn0 + p * 16 + (sub >> 1) * 8 + r8;
                int col = kk + (sub & 1) * 8;
                uint32_t t4[4];
                ldsm_x4(t4, bBase + (row * SROW + col) * 2);
                bfrag[p * 2 + 0][0] = t4[0]; bfrag[p * 2 + 0][1] = t4[1];
                bfrag[p * 2 + 1][0] = t4[2]; bfrag[p * 2 + 1][1] = t4[3];
            }
            #pragma unroll
            for (int mt = 0; mt < 4; mt++)
                #pragma unroll
                for (int nt = 0; nt < 8; nt++)
                    mma16816(acc[mt][nt], afrag[mt], bfrag[nt]);
        }
        __syncthreads();
        buf ^= 1;
    }

    // epilogue: sigmoid + row reduce
    float rs[4][2];
    #pragma unroll
    for (int mt = 0; mt < 4; mt++) { rs[mt][0] = 0.0f; rs[mt][1] = 0.0f; }
    #pragma unroll
    for (int mt = 0; mt < 4; mt++)
        #pragma unroll
        for (int nt = 0; nt < 8; nt++) {
            rs[mt][0] += __fdividef(1.0f, 1.0f + __expf(-acc[mt][nt][0]))
                       + __fdividef(1.0f, 1.0f + __expf(-acc[mt][nt][1]));
            rs[mt][1] += __fdividef(1.0f, 1.0f + __expf(-acc[mt][nt][2]))
                       + __fdividef(1.0f, 1.0f + __expf(-acc[mt][nt][3]));
        }
    #pragma unroll
    for (int mt = 0; mt < 4; mt++)
        #pragma unroll
        for (int h = 0; h < 2; h++) {
            rs[mt][h] += __shfl_xor_sync(0xffffffffu, rs[mt][h], 1);
            rs[mt][h] += __shfl_xor_sync(0xffffffffu, rs[mt][h], 2);
        }
    if ((lane & 3) == 0) {
        const int rq = lane >> 2;
        const int wn = wid >> 1;
        #pragma unroll
        for (int mt = 0; mt < 4; mt++) {
            s_rows[wn * 128 + wm0 + mt * 16 + 0 + rq] = rs[mt][0];
            s_rows[wn * 128 + wm0 + mt * 16 + 8 + rq] = rs[mt][1];
        }
    }
    __syncthreads();
    if (tid < 128) {
        g_part[blockIdx.x][i0 + tid] = s_rows[tid] + s_rows[128 + tid] +
                                       s_rows[256 + tid] + s_rows[384 + tid];
    }
}

// ===========================================================================
// S3: reduce 32 partials + broadcast. One warp per output row.
// ===========================================================================
__global__ void reduce_bcast_kernel(float* __restrict__ out) {
    const int wid = threadIdx.x >> 5, lane = threadIdx.x & 31;
    const int row = blockIdx.x * 8 + wid;
    float s = g_part[lane][row];
    #pragma unroll
    for (int d = 16; d > 0; d >>= 1) s += __shfl_xor_sync(0xffffffffu, s, d);
    const float v = s * (1.0f / 256.0f);
    float4* dst = (float4*)(out + (size_t)row * HDIM);
    const float4 vv = make_float4(v, v, v, v);
    dst[lane]      = vv;
    dst[lane + 32] = vv;
}

// ===========================================================================
extern "C" void kernel_launch(void* const* d_in, const int* in_sizes, int n_in,
                              void* d_out, int out_size) {
    const float* y_a = (const float*)d_in[0];
    const float* y_b = (const float*)d_in[1];
    const float* W   = (const float*)d_in[2];
    const float* b   = (const float*)d_in[3];
    float* out = (float*)d_out;

    cudaFuncSetAttribute(fused_hmma_kernel,
                         cudaFuncAttributeMaxDynamicSharedMemorySize, FUSED_SMEM);

    convert_all_kernel<<<4160, 256>>>(y_a, y_b, W);
    proj_hmma_kernel<<<dim3(2, 64), 256>>>(b);
    fused_hmma_kernel<<<dim3(NUSR / 256, NUSR / 128), 256, FUSED_SMEM>>>();
    reduce_bcast_kernel<<<NUSR / 8, 256>>>(out);
}

// round 6
// speedup vs baseline: 8.2715x; 1.2774x over previous
#include <cuda_runtime.h>
#include <cuda_bf16.h>
#include <cstdint>

// ---------------------------------------------------------------------------
// miScore: out[i,k] = (1/256) * sum_j sigmoid( y_a[i,:] . (W @ y_b[j,:] + b) )
//
// S0: convert y_a, y_b, W fp32 -> bf16 (one kernel)
// S1: proj = y_b @ W^T + b   (HMMA bf16, bias epilogue, bf16 store)
// S2: fused HMMA bf16 GEMM (y_a @ proj^T) + sigmoid + row partials
//     CTA 128x128, 128 thr (4 warps, warp tile 64x64), BK=64 dbl-buffered,
//     2 CTAs/SM. sigmoid via tanh.approx (1 MUFU instead of 2).
// S3: reduce 64 partials + broadcast (one warp per row)
// ---------------------------------------------------------------------------

#define NUSR 8192
#define HDIM 256

__device__ __align__(16) __nv_bfloat16 g_ya[NUSR * HDIM];     // 4 MB
__device__ __align__(16) __nv_bfloat16 g_yb[NUSR * HDIM];     // 4 MB
__device__ __align__(16) __nv_bfloat16 g_wb[HDIM * HDIM];     // 128 KB
__device__ __align__(16) __nv_bfloat16 g_projb[NUSR * HDIM];  // 4 MB
__device__ float g_part[64][NUSR];                            // 2 MB
__device__ float g_s[NUSR];

// ---------------- cp.async helpers ----------------
__device__ __forceinline__ void cp_async16(uint32_t dst, const void* src) {
    asm volatile("cp.async.cg.shared.global [%0], [%1], 16;" :: "r"(dst), "l"(src));
}
#define CP_COMMIT() asm volatile("cp.async.commit_group;" ::: "memory")
#define CP_WAIT1()  asm volatile("cp.async.wait_group 1;" ::: "memory")
#define CP_WAIT0()  asm volatile("cp.async.wait_group 0;" ::: "memory")

// ---------------- mma / ldmatrix ----------------
__device__ __forceinline__ void ldsm_x4(uint32_t* r, uint32_t addr) {
    asm volatile("ldmatrix.sync.aligned.m8n8.x4.shared.b16 {%0,%1,%2,%3}, [%4];"
                 : "=r"(r[0]), "=r"(r[1]), "=r"(r[2]), "=r"(r[3]) : "r"(addr));
}
__device__ __forceinline__ void mma16816(float* c, const uint32_t* a, const uint32_t* b) {
    asm volatile(
        "mma.sync.aligned.m16n8k16.row.col.f32.bf16.bf16.f32 "
        "{%0,%1,%2,%3}, {%4,%5,%6,%7}, {%8,%9}, {%0,%1,%2,%3};"
        : "+f"(c[0]), "+f"(c[1]), "+f"(c[2]), "+f"(c[3])
        : "r"(a[0]), "r"(a[1]), "r"(a[2]), "r"(a[3]), "r"(b[0]), "r"(b[1]));
}
__device__ __forceinline__ float fast_tanh(float x) {
    float t;
    asm("tanh.approx.f32 %0, %1;" : "=f"(t) : "f"(x));
    return t;
}

// ===========================================================================
// S0: convert y_a, y_b, W to bf16. One float4 per thread.
// ===========================================================================
__global__ void convert_all_kernel(const float* __restrict__ ya,
                                   const float* __restrict__ yb,
                                   const float* __restrict__ W) {
    const int idx = blockIdx.x * 256 + threadIdx.x;
    const float* src;
    __nv_bfloat162* dst;
    int off;
    if (idx < 524288) {
        src = ya; dst = (__nv_bfloat162*)g_ya; off = idx;
    } else if (idx < 1048576) {
        src = yb; dst = (__nv_bfloat162*)g_yb; off = idx - 524288;
    } else {
        src = W;  dst = (__nv_bfloat162*)g_wb; off = idx - 1048576;
    }
    float4 v = ((const float4*)src)[off];
    dst[off * 2 + 0] = __floats2bfloat162_rn(v.x, v.y);
    dst[off * 2 + 1] = __floats2bfloat162_rn(v.z, v.w);
}

// ===========================================================================
// S1: proj = y_b @ W^T + b (HMMA). CTA 128(Mj) x 128(Ns); grid (2, 64).
// ===========================================================================
#define PSROW 40
#define PA_BYTES (128 * PSROW * 2)
#define PBUF_BYTES (2 * PA_BYTES)

__global__ void __launch_bounds__(256, 1) proj_hmma_kernel(const float* __restrict__ bias) {
    __shared__ __align__(16) char smem[2 * PBUF_BYTES];
    const uint32_t sbase = (uint32_t)__cvta_generic_to_shared(smem);

    const int tid = threadIdx.x;
    const int wid = tid >> 5, lane = tid & 31;
    const int wm0 = (wid & 1) * 64;
    const int wn0 = (wid >> 1) * 32;
    const int j0 = blockIdx.y * 128;
    const int s0 = blockIdx.x * 128;

    float acc[4][4][4];
    #pragma unroll
    for (int mt = 0; mt < 4; mt++)
        #pragma unroll
        for (int nt = 0; nt < 4; nt++)
            #pragma unroll
            for (int e = 0; e < 4; e++) acc[mt][nt][e] = 0.0f;

    auto load_chunk = [&](uint32_t dstb, int kt) {
        #pragma unroll
        for (int t = 0; t < 4; t++) {
            int g = tid + t * 256;
            if (g < 512) {
                int row = g >> 2, c = g & 3;
                cp_async16(dstb + (row * PSROW + c * 8) * 2,
                           g_yb + (size_t)(j0 + row) * HDIM + kt + c * 8);
            } else {
                int gb = g - 512;
                int row = gb >> 2, c = gb & 3;
                cp_async16(dstb + PA_BYTES + (row * PSROW + c * 8) * 2,
                           g_wb + (size_t)(s0 + row) * HDIM + kt + c * 8);
            }
        }
        CP_COMMIT();
    };

    load_chunk(sbase, 0);

    const int sub = lane >> 3, r8 = lane & 7;

    int buf = 0;
    #pragma unroll 1
    for (int it = 0; it < 8; it++) {
        if (it < 7) { load_chunk(sbase + (1 - buf) * PBUF_BYTES, (it + 1) * 32); CP_WAIT1(); }
        else        { CP_WAIT0(); }
        __syncthreads();

        const uint32_t aBase = sbase + buf * PBUF_BYTES;
        const uint32_t bBase = aBase + PA_BYTES;

        #pragma unroll
        for (int kk = 0; kk < 32; kk += 16) {
            uint32_t afrag[4][4];
            #pragma unroll
            for (int mt = 0; mt < 4; mt++) {
                int row = wm0 + mt * 16 + (sub & 1) * 8 + r8;
                int col = kk + (sub >> 1) * 8;
                ldsm_x4(afrag[mt], aBase + (row * PSROW + col) * 2);
            }
            uint32_t bfrag[4][2];
            #pragma unroll
            for (int p = 0; p < 2; p++) {
                int row = wn0 + p * 16 + (sub >> 1) * 8 + r8;
                int col = kk + (sub & 1) * 8;
                uint32_t t4[4];
                ldsm_x4(t4, bBase + (row * PSROW + col) * 2);
                bfrag[p * 2 + 0][0] = t4[0]; bfrag[p * 2 + 0][1] = t4[1];
                bfrag[p * 2 + 1][0] = t4[2]; bfrag[p * 2 + 1][1] = t4[3];
            }
            #pragma unroll
            for (int mt = 0; mt < 4; mt++)
                #pragma unroll
                for (int nt = 0; nt < 4; nt++)
                    mma16816(acc[mt][nt], afrag[mt], bfrag[nt]);
        }
        __syncthreads();
        buf ^= 1;
    }

    #pragma unroll
    for (int nt = 0; nt < 4; nt++) {
        const int gc = s0 + wn0 + nt * 8 + 2 * (lane & 3);
        const float b0 = bias[gc], b1 = bias[gc + 1];
        #pragma unroll
        for (int mt = 0; mt < 4; mt++) {
            const int rlo = j0 + wm0 + mt * 16 + (lane >> 2);
            *((__nv_bfloat162*)&g_projb[(size_t)rlo * HDIM + gc]) =
                __floats2bfloat162_rn(acc[mt][nt][0] + b0, acc[mt][nt][1] + b1);
            *((__nv_bfloat162*)&g_projb[(size_t)(rlo + 8) * HDIM + gc]) =
                __floats2bfloat162_rn(acc[mt][nt][2] + b0, acc[mt][nt][3] + b1);
        }
    }
}

// ===========================================================================
// S2: fused HMMA bf16 GEMM + sigmoid + row partials.
//   CTA 128(M=i) x 128(N=j); 4 warps as 2(M) x 2(N); warp tile 64x64.
//   K=256 in 4 chunks of 64, double-buffered; 2 CTAs/SM.
// ===========================================================================
#define SROW 72
#define SA_BYTES (128 * SROW * 2)            // 18432
#define SB_BYTES (128 * SROW * 2)            // 18432
#define BUF_BYTES (SA_BYTES + SB_BYTES)      // 36864
#define SROWS_OFF (2 * BUF_BYTES)            // 73728
#define FUSED_SMEM (SROWS_OFF + 2 * 128 * 4) // 74752

__global__ void __launch_bounds__(128, 2) fused_hmma_kernel() {
    extern __shared__ __align__(16) char smem[];
    const uint32_t sbase = (uint32_t)__cvta_generic_to_shared(smem);
    float* s_rows = (float*)(smem + SROWS_OFF);   // [2][128]

    const int tid = threadIdx.x;
    const int wid = tid >> 5, lane = tid & 31;
    const int wm0 = (wid & 1) * 64;            // warp M offset (0/64)
    const int wn0 = (wid >> 1) * 64;           // warp N offset (0/64)
    const int i0 = blockIdx.y * 128;
    const int j0 = blockIdx.x * 128;

    float acc[4][8][4];
    #pragma unroll
    for (int mt = 0; mt < 4; mt++)
        #pragma unroll
        for (int nt = 0; nt < 8; nt++)
            #pragma unroll
            for (int e = 0; e < 4; e++) acc[mt][nt][e] = 0.0f;

    // loader: A 1024 + B 1024 granules of 16 B; 16 per thread
    auto load_chunk = [&](uint32_t dstb, int kt) {
        #pragma unroll
        for (int t = 0; t < 16; t++) {
            int g = tid + t * 128;
            if (g < 1024) {
                int row = g >> 3, c = g & 7;
                cp_async16(dstb + (row * SROW + c * 8) * 2,
                           g_ya + (size_t)(i0 + row) * HDIM + kt + c * 8);
            } else {
                int gb = g - 1024;
                int row = gb >> 3, c = gb & 7;
                cp_async16(dstb + SA_BYTES + (row * SROW + c * 8) * 2,
                           g_projb + (size_t)(j0 + row) * HDIM + kt + c * 8);
            }
        }
        CP_COMMIT();
    };

    load_chunk(sbase, 0);

    const int sub = lane >> 3, r8 = lane & 7;

    int buf = 0;
    #pragma unroll 1
    for (int it = 0; it < 4; it++) {
        if (it < 3) { load_chunk(sbase + (1 - buf) * BUF_BYTES, (it + 1) * 64); CP_WAIT1(); }
        else        { CP_WAIT0(); }
        __syncthreads();

        const uint32_t aBase = sbase + buf * BUF_BYTES;
        const uint32_t bBase = aBase + SA_BYTES;

        #pragma unroll
        for (int kk = 0; kk < 64; kk += 16) {
            uint32_t afrag[4][4];
            #pragma unroll
            for (int mt = 0; mt < 4; mt++) {
                int row = wm0 + mt * 16 + (sub & 1) * 8 + r8;
                int col = kk + (sub >> 1) * 8;
                ldsm_x4(afrag[mt], aBase + (row * SROW + col) * 2);
            }
            uint32_t bfrag[8][2];
            #pragma unroll
            for (int p = 0; p < 4; p++) {
                int row = wn0 + p * 16 + (sub >> 1) * 8 + r8;
                int col = kk + (sub & 1) * 8;
                uint32_t t4[4];
                ldsm_x4(t4, bBase + (row * SROW + col) * 2);
                bfrag[p * 2 + 0][0] = t4[0]; bfrag[p * 2 + 0][1] = t4[1];
                bfrag[p * 2 + 1][0] = t4[2]; bfrag[p * 2 + 1][1] = t4[3];
            }
            #pragma unroll
            for (int mt = 0; mt < 4; mt++)
                #pragma unroll
                for (int nt = 0; nt < 8; nt++)
                    mma16816(acc[mt][nt], afrag[mt], bfrag[nt]);
        }
        __syncthreads();
        buf ^= 1;
    }

    // epilogue: sigmoid(x) = 0.5*tanh(x/2) + 0.5 ; accumulate 0.5*tanh(x/2),
    // add the 0.5*count constant at the end.
    float rs[4][2];
    #pragma unroll
    for (int mt = 0; mt < 4; mt++) { rs[mt][0] = 0.0f; rs[mt][1] = 0.0f; }
    #pragma unroll
    for (int mt = 0; mt < 4; mt++)
        #pragma unroll
        for (int nt = 0; nt < 8; nt++) {
            rs[mt][0] += 0.5f * fast_tanh(0.5f * acc[mt][nt][0])
                       + 0.5f * fast_tanh(0.5f * acc[mt][nt][1]);
            rs[mt][1] += 0.5f * fast_tanh(0.5f * acc[mt][nt][2])
                       + 0.5f * fast_tanh(0.5f * acc[mt][nt][3]);
        }
    #pragma unroll
    for (int mt = 0; mt < 4; mt++)
        #pragma unroll
        for (int h = 0; h < 2; h++) {
            rs[mt][h] += __shfl_xor_sync(0xffffffffu, rs[mt][h], 1);
            rs[mt][h] += __shfl_xor_sync(0xffffffffu, rs[mt][h], 2);
        }
    if ((lane & 3) == 0) {
        const int rq = lane >> 2;
        const int wn = wid >> 1;
        // each rs bucket now covers 64 columns -> add 64 * 0.5 = 32
        #pragma unroll
        for (int mt = 0; mt < 4; mt++) {
            s_rows[wn * 128 + wm0 + mt * 16 + 0 + rq] = rs[mt][0] + 32.0f;
            s_rows[wn * 128 + wm0 + mt * 16 + 8 + rq] = rs[mt][1] + 32.0f;
        }
    }
    __syncthreads();
    g_part[blockIdx.x][i0 + tid] = s_rows[tid] + s_rows[128 + tid];
}

// ===========================================================================
// S3: reduce 64 partials + broadcast. One warp per output row.
// ===========================================================================
__global__ void reduce_bcast_kernel(float* __restrict__ out) {
    const int wid = threadIdx.x >> 5, lane = threadIdx.x & 31;
    const int row = blockIdx.x * 8 + wid;
    float s = g_part[lane][row] + g_part[lane + 32][row];
    #pragma unroll
    for (int d = 16; d > 0; d >>= 1) s += __shfl_xor_sync(0xffffffffu, s, d);
    const float v = s * (1.0f / 256.0f);
    float4* dst = (float4*)(out + (size_t)row * HDIM);
    const float4 vv = make_float4(v, v, v, v);
    dst[lane]      = vv;
    dst[lane + 32] = vv;
}

// ===========================================================================
extern "C" void kernel_launch(void* const* d_in, const int* in_sizes, int n_in,
                              void* d_out, int out_size) {
    const float* y_a = (const float*)d_in[0];
    const float* y_b = (const float*)d_in[1];
    const float* W   = (const float*)d_in[2];
    const float* b   = (const float*)d_in[3];
    float* out = (float*)d_out;

    cudaFuncSetAttribute(fused_hmma_kernel,
                         cudaFuncAttributeMaxDynamicSharedMemorySize, FUSED_SMEM);

    convert_all_kernel<<<4160, 256>>>(y_a, y_b, W);
    proj_hmma_kernel<<<dim3(2, 64), 256>>>(b);
    fused_hmma_kernel<<<dim3(NUSR / 128, NUSR / 128), 128, FUSED_SMEM>>>();
    reduce_bcast_kernel<<<NUSR / 8, 256>>>(out);
}